// round 1
// baseline (speedup 1.0000x reference)
#include <cuda_runtime.h>
#include <math.h>

#define NN 50000
#define NE 800000
#define DD 128
#define BIGF 1000000000.0f

// ---------------- scratch (static device globals; no allocs) ----------------
__device__ float        g_z[NN * DD];      // z = h@W + b   (25.6 MB)
__device__ float        g_s[NN];           // z . w_src
__device__ float        g_t[NN];           // z . w_dst
__device__ float        g_e[NE];           // e, later ex
__device__ unsigned int g_m[NN];           // segment max (monotonic uint enc)
__device__ float        g_denom[NN];       // segment sum of ex
__device__ float        g_bsum[NN];        // segment sum of sigma
__device__ float        g_hnew[NN * DD];   // aggregated output (25.6 MB)
__device__ float        g_colsum[DD];
__device__ float        g_colsq[DD];

// monotonic float<->uint mapping for atomicMax on floats
__device__ __forceinline__ unsigned fenc(float f) {
    int i = __float_as_int(f);
    return (i < 0) ? ~((unsigned)i) : (((unsigned)i) | 0x80000000u);
}
__device__ __forceinline__ float fdec(unsigned u) {
    int i = (u & 0x80000000u) ? (int)(u & 0x7fffffffu) : ~((int)u);
    return __int_as_float(i);
}

__device__ __forceinline__ float clamp_inf(float v) {
    return isinf(v) ? BIGF : v;
}

// ---------------- kernel 0: init accumulators ----------------
__global__ void k_init() {
    int i = blockIdx.x * blockDim.x + threadIdx.x;   // grid sized to NN*DD
    if (i < NN * DD) g_hnew[i] = 0.0f;
    if (i < NN) { g_m[i] = 0u; g_denom[i] = 0.0f; g_bsum[i] = 0.0f; }
    if (i < DD) { g_colsum[i] = 0.0f; g_colsq[i] = 0.0f; }
}

// ---------------- kernel 1: z = h @ W + b (64x128 tile per block) ----------------
__global__ __launch_bounds__(256) void k_gemm(const float* __restrict__ H,
                                              const float* __restrict__ W,
                                              const float* __restrict__ B) {
    __shared__ float Ws[32 * 128];   // current K-chunk of W   (16 KB)
    __shared__ float As[32 * 64];    // A tile transposed [k][row] (8 KB)

    const int tid = threadIdx.x;
    const int tx = tid & 31;         // col group: cols tx*4 .. tx*4+3
    const int ty = tid >> 5;         // row group: rows ty*8 .. ty*8+7
    const int row0 = blockIdx.x * 64;

    float acc[8][4];
#pragma unroll
    for (int r = 0; r < 8; r++)
#pragma unroll
        for (int c = 0; c < 4; c++) acc[r][c] = 0.0f;

    for (int k0 = 0; k0 < 128; k0 += 32) {
        __syncthreads();
        // load W chunk: 32x128 floats = 1024 float4
        const float4* wsrc = (const float4*)(W + k0 * 128);
#pragma unroll
        for (int i = tid; i < 1024; i += 256) ((float4*)Ws)[i] = wsrc[i];
        // load A tile transposed: 64 rows x 32 k
#pragma unroll
        for (int l = 0; l < 2; l++) {
            int f = tid * 2 + l;          // float4 index 0..511
            int row = f >> 3;             // 0..63
            int kk = (f & 7) * 4;         // 0,4,...,28
            float4 v = make_float4(0.f, 0.f, 0.f, 0.f);
            int grow = row0 + row;
            if (grow < NN) v = *(const float4*)&H[grow * 128 + k0 + kk];
            As[(kk + 0) * 64 + row] = v.x;
            As[(kk + 1) * 64 + row] = v.y;
            As[(kk + 2) * 64 + row] = v.z;
            As[(kk + 3) * 64 + row] = v.w;
        }
        __syncthreads();
#pragma unroll
        for (int k = 0; k < 32; k++) {
            float4 b4 = *(float4*)&Ws[k * 128 + tx * 4];
            float4 a0 = *(float4*)&As[k * 64 + ty * 8];
            float4 a1 = *(float4*)&As[k * 64 + ty * 8 + 4];
            float av[8] = {a0.x, a0.y, a0.z, a0.w, a1.x, a1.y, a1.z, a1.w};
#pragma unroll
            for (int r = 0; r < 8; r++) {
                acc[r][0] += av[r] * b4.x;
                acc[r][1] += av[r] * b4.y;
                acc[r][2] += av[r] * b4.z;
                acc[r][3] += av[r] * b4.w;
            }
        }
    }

    float4 bias = *(const float4*)&B[tx * 4];
#pragma unroll
    for (int r = 0; r < 8; r++) {
        int grow = row0 + ty * 8 + r;
        if (grow < NN) {
            float4 v;
            v.x = clamp_inf(acc[r][0] + bias.x);
            v.y = clamp_inf(acc[r][1] + bias.y);
            v.z = clamp_inf(acc[r][2] + bias.z);
            v.w = clamp_inf(acc[r][3] + bias.w);
            *(float4*)&g_z[grow * 128 + tx * 4] = v;
        }
    }
}

// ---------------- kernel 2: per-node attention dots ----------------
__global__ __launch_bounds__(256) void k_st(const float* __restrict__ AW) {
    int warp = threadIdx.x >> 5;
    int lane = threadIdx.x & 31;
    int n = blockIdx.x * 8 + warp;
    if (n >= NN) return;
    float4 z4 = *(const float4*)&g_z[n * DD + lane * 4];
    float4 ws = *(const float4*)&AW[lane * 4];
    float4 wd = *(const float4*)&AW[DD + lane * 4];
    float s = z4.x * ws.x + z4.y * ws.y + z4.z * ws.z + z4.w * ws.w;
    float t = z4.x * wd.x + z4.y * wd.y + z4.z * wd.z + z4.w * wd.w;
#pragma unroll
    for (int o = 16; o > 0; o >>= 1) {
        s += __shfl_down_sync(0xffffffffu, s, o);
        t += __shfl_down_sync(0xffffffffu, t, o);
    }
    if (lane == 0) { g_s[n] = s; g_t[n] = t; }
}

// ---------------- kernel 3: edge logits + segment max ----------------
__global__ void k_edge1(const int* __restrict__ src, const int* __restrict__ dst,
                        const float* __restrict__ attnb) {
    int i = blockIdx.x * blockDim.x + threadIdx.x;
    if (i >= NE) return;
    float a = g_s[src[i]] + g_t[dst[i]] + attnb[0];
    a = clamp_inf(a);
    float e = (a > 0.0f) ? a : 0.01f * a;   // leaky relu
    g_e[i] = e;
    atomicMax(&g_m[dst[i]], fenc(e));
}

// ---------------- kernel 4: exp + segment sums ----------------
__global__ void k_edge2(const int* __restrict__ src, const int* __restrict__ dst,
                        const float* __restrict__ sigma) {
    int i = blockIdx.x * blockDim.x + threadIdx.x;
    if (i >= NE) return;
    int d = dst[i];
    float m = fdec(g_m[d]);
    float ex = __expf(g_e[i] - m);
    g_e[i] = ex;
    atomicAdd(&g_denom[d], ex);
    atomicAdd(&g_bsum[d], sigma[i]);
}

// ---------------- kernel 5: weighted scatter-aggregate (1 warp / edge) ----------------
__global__ __launch_bounds__(256) void k_agg(const int* __restrict__ src,
                                             const int* __restrict__ dst,
                                             const float* __restrict__ sigma) {
    int wg = (blockIdx.x * blockDim.x + threadIdx.x) >> 5;
    int lane = threadIdx.x & 31;
    if (wg >= NE) return;
    int s_ = 0, d_ = 0;
    float coef = 0.0f;
    if (lane == 0) {
        d_ = dst[wg];
        s_ = src[wg];
        float ex = g_e[wg];
        float sg = sigma[wg];
        coef = (ex / g_denom[d_]) * (sg / (g_bsum[d_] + 1e-6f));
    }
    coef = __shfl_sync(0xffffffffu, coef, 0);
    s_ = __shfl_sync(0xffffffffu, s_, 0);
    d_ = __shfl_sync(0xffffffffu, d_, 0);

    float4 zv = *(const float4*)&g_z[s_ * DD + lane * 4];
    float vx = coef * zv.x, vy = coef * zv.y, vz = coef * zv.z, vw = coef * zv.w;
    float* p = &g_hnew[d_ * DD + lane * 4];
    asm volatile("red.global.add.v4.f32 [%0], {%1, %2, %3, %4};"
                 :: "l"(p), "f"(vx), "f"(vy), "f"(vz), "f"(vw) : "memory");
}

// ---------------- kernel 6: column stats for BN ----------------
__global__ void k_stats() {
    int c = threadIdx.x;           // 128 threads
    float s = 0.0f, q = 0.0f;
    for (int r = blockIdx.x; r < NN; r += gridDim.x) {
        float v = clamp_inf(g_hnew[r * DD + c]);
        s += v;
        q += v * v;
    }
    atomicAdd(&g_colsum[c], s);
    atomicAdd(&g_colsq[c], q);
}

// ---------------- kernel 7: batchnorm + elu ----------------
__global__ void k_bn(float* __restrict__ out, const float* __restrict__ gamma,
                     const float* __restrict__ beta) {
    int idx = blockIdx.x * blockDim.x + threadIdx.x;
    if (idx >= NN * DD) return;
    int c = idx & 127;
    const float inv_n = 1.0f / (float)NN;
    float mu = g_colsum[c] * inv_n;
    float var = g_colsq[c] * inv_n - mu * mu;
    float v = clamp_inf(g_hnew[idx]);
    float xb = (v - mu) * rsqrtf(var + 1e-5f) * gamma[c] + beta[c];
    out[idx] = (xb > 0.0f) ? xb : expm1f(xb);   // elu
}

// ---------------- launcher ----------------
extern "C" void kernel_launch(void* const* d_in, const int* in_sizes, int n_in,
                              void* d_out, int out_size) {
    const float* h     = (const float*)d_in[0];
    const int*   src   = (const int*)d_in[1];
    const int*   dst   = (const int*)d_in[2];
    const float* sigma = (const float*)d_in[3];
    const float* fcw   = (const float*)d_in[4];
    const float* fcb   = (const float*)d_in[5];
    const float* attnw = (const float*)d_in[6];
    const float* attnb = (const float*)d_in[7];
    const float* gamma = (const float*)d_in[8];
    const float* beta  = (const float*)d_in[9];
    float* out = (float*)d_out;

    k_init<<<(NN * DD + 255) / 256, 256>>>();
    k_gemm<<<(NN + 63) / 64, 256>>>(h, fcw, fcb);
    k_st<<<(NN + 7) / 8, 256>>>(attnw);
    k_edge1<<<(NE + 255) / 256, 256>>>(src, dst, attnb);
    k_edge2<<<(NE + 255) / 256, 256>>>(src, dst, sigma);
    k_agg<<<NE / 8, 256>>>(src, dst, sigma);       // 1 warp per edge
    k_stats<<<512, 128>>>();
    k_bn<<<(NN * DD + 255) / 256, 256>>>(out, gamma, beta);
}